// round 2
// baseline (speedup 1.0000x reference)
#include <cuda_runtime.h>

#define KCODES 512
#define DCH 64
#define NPIX (32*64*64)        // 131072 pixels
#define TOTAL (NPIX*DCH)       // 8388608 output tensor elements
#define TPB 256
#define PX_PER_BLOCK 512       // 2 pixels per thread
#define NBLOCKS (NPIX/PX_PER_BLOCK)  // 256

typedef unsigned long long u64;

__device__ double g_partials[NBLOCKS];

__device__ __forceinline__ u64 fma2(u64 a, u64 b, u64 c) {
    u64 d; asm("fma.rn.f32x2 %0,%1,%2,%3;" : "=l"(d) : "l"(a), "l"(b), "l"(c)); return d;
}
__device__ __forceinline__ u64 add2(u64 a, u64 b) {
    u64 d; asm("add.rn.f32x2 %0,%1,%2;" : "=l"(d) : "l"(a), "l"(b)); return d;
}
__device__ __forceinline__ u64 pack2(float lo, float hi) {
    u64 d; asm("mov.b64 %0,{%1,%2};" : "=l"(d) : "f"(lo), "f"(hi)); return d;
}
__device__ __forceinline__ void unpack2(u64 v, float& lo, float& hi) {
    asm("mov.b64 {%0,%1},%2;" : "=f"(lo), "=f"(hi) : "l"(v));
}

// dynamic smem: [KCODES*DCH] codebook, [KCODES] e2, [TPB] double reduce
extern __shared__ float smem[];

__global__ __launch_bounds__(TPB, 1)
void vq_main(const float* __restrict__ lat, const float* __restrict__ W,
             float* __restrict__ out) {
    float* sW  = smem;
    float* sE2 = smem + KCODES * DCH;
    double* sRed = (double*)(sE2 + KCODES);

    const int tid = threadIdx.x;

    // ---- cooperative codebook load (coalesced float4) ----
    {
        float4* d4 = (float4*)sW;
        const float4* s4 = (const float4*)W;
        #pragma unroll
        for (int i = 0; i < (KCODES * DCH / 4) / TPB; i++)
            d4[tid + i * TPB] = s4[tid + i * TPB];
    }
    __syncthreads();

    // ---- e2[k] = sum_j W[k][j]^2 (warp per row, conflict-free) ----
    {
        int warp = tid >> 5, lane = tid & 31;
        for (int r = warp; r < KCODES; r += TPB / 32) {
            float v0 = sW[r * DCH + lane];
            float v1 = sW[r * DCH + 32 + lane];
            float s = v0 * v0 + v1 * v1;   // e2 ~8e-5, rounding irrelevant (<1e-10)
            #pragma unroll
            for (int o = 16; o; o >>= 1) s += __shfl_xor_sync(0xffffffffu, s, o);
            if (lane == 0) sE2[r] = s;
        }
    }
    __syncthreads();

    // ---- per-thread: two pixels ----
    const int n0 = blockIdx.x * PX_PER_BLOCK + tid;   // pixel A
    const int n1 = n0 + TPB;                          // pixel B
    const int b  = n0 >> 12;                          // 4096 px per batch image
    const int base = b << 18;                         // b * D * 4096
    const int p0 = n0 & 4095, p1 = n1 & 4095;

    // load x for both pixels; pack channel pairs into f32x2 regs
    u64 xa[32], xb[32];
    float x2a = 0.0f, x2b = 0.0f;
    #pragma unroll
    for (int j = 0; j < 32; j++) {
        float a0 = lat[base + ((2 * j)     << 12) + p0];
        float a1 = lat[base + ((2 * j + 1) << 12) + p0];
        float b0 = lat[base + ((2 * j)     << 12) + p1];
        float b1 = lat[base + ((2 * j + 1) << 12) + p1];
        xa[j] = pack2(a0, a1);
        xb[j] = pack2(b0, b1);
        // sequential sum of rounded squares (mimic elementwise-mul + reduce)
        x2a = __fadd_rn(x2a, __fmul_rn(a0, a0));
        x2a = __fadd_rn(x2a, __fmul_rn(a1, a1));
        x2b = __fadd_rn(x2b, __fmul_rn(b0, b0));
        x2b = __fadd_rn(x2b, __fmul_rn(b1, b1));
    }

    float bestA = 3.402823466e38f, bestB = 3.402823466e38f;
    int idxA = 0, idxB = 0;

    #pragma unroll 2
    for (int k = 0; k < KCODES; k++) {
        const ulonglong2* e = (const ulonglong2*)(sW + k * DCH);
        u64 a0 = 0ull, a1 = 0ull, b0 = 0ull, b1 = 0ull;
        #pragma unroll
        for (int i = 0; i < 16; i++) {
            ulonglong2 ev = e[i];      // 4 floats of code k (broadcast LDS.128)
            a0 = fma2(xa[2 * i],     ev.x, a0);
            a1 = fma2(xa[2 * i + 1], ev.y, a1);
            b0 = fma2(xb[2 * i],     ev.x, b0);
            b1 = fma2(xb[2 * i + 1], ev.y, b1);
        }
        const float e2k = sE2[k];
        u64 sa = add2(a0, a1);
        u64 sb = add2(b0, b1);
        float lo, hi;
        unpack2(sa, lo, hi); float dotA = __fadd_rn(lo, hi);
        unpack2(sb, lo, hi); float dotB = __fadd_rn(lo, hi);
        // dist = round(round(x2+e2) - 2*dot); fma(-2,dot,s) rounds identically
        float dA = __fmaf_rn(-2.0f, dotA, __fadd_rn(x2a, e2k));
        float dB = __fmaf_rn(-2.0f, dotB, __fadd_rn(x2b, e2k));
        if (dA < bestA) { bestA = dA; idxA = k; }   // strict <: first index wins ties
        if (dB < bestB) { bestB = dB; idxB = k; }
    }

    // ---- gather chosen codes, write output, accumulate SSE ----
    double sse = 0.0;
    {
        const float4* q4 = (const float4*)(sW + idxA * DCH);
        #pragma unroll
        for (int i = 0; i < 16; i++) {
            float4 q = q4[i];
            float xlo, xhi;
            unpack2(xa[2 * i], xlo, xhi);
            float d0 = q.x - xlo, d1 = q.y - xhi;
            unpack2(xa[2 * i + 1], xlo, xhi);
            float d2 = q.z - xlo, d3 = q.w - xhi;
            out[base + ((4 * i    ) << 12) + p0] = q.x;
            out[base + ((4 * i + 1) << 12) + p0] = q.y;
            out[base + ((4 * i + 2) << 12) + p0] = q.z;
            out[base + ((4 * i + 3) << 12) + p0] = q.w;
            sse += (double)__fmul_rn(d0, d0) + (double)__fmul_rn(d1, d1)
                 + (double)__fmul_rn(d2, d2) + (double)__fmul_rn(d3, d3);
        }
    }
    {
        const float4* q4 = (const float4*)(sW + idxB * DCH);
        #pragma unroll
        for (int i = 0; i < 16; i++) {
            float4 q = q4[i];
            float xlo, xhi;
            unpack2(xb[2 * i], xlo, xhi);
            float d0 = q.x - xlo, d1 = q.y - xhi;
            unpack2(xb[2 * i + 1], xlo, xhi);
            float d2 = q.z - xlo, d3 = q.w - xhi;
            out[base + ((4 * i    ) << 12) + p1] = q.x;
            out[base + ((4 * i + 1) << 12) + p1] = q.y;
            out[base + ((4 * i + 2) << 12) + p1] = q.z;
            out[base + ((4 * i + 3) << 12) + p1] = q.w;
            sse += (double)__fmul_rn(d0, d0) + (double)__fmul_rn(d1, d1)
                 + (double)__fmul_rn(d2, d2) + (double)__fmul_rn(d3, d3);
        }
    }

    // ---- deterministic block reduction of sse ----
    sRed[tid] = sse;
    __syncthreads();
    #pragma unroll
    for (int o = TPB / 2; o > 0; o >>= 1) {
        if (tid < o) sRed[tid] += sRed[tid + o];
        __syncthreads();
    }
    if (tid == 0) g_partials[blockIdx.x] = sRed[0];
}

__global__ void vq_finish(float* __restrict__ out, int out_size) {
    __shared__ double s[NBLOCKS];
    int t = threadIdx.x;
    s[t] = g_partials[t];
    __syncthreads();
    #pragma unroll
    for (int o = NBLOCKS / 2; o > 0; o >>= 1) {
        if (t < o) s[t] += s[t + o];
        __syncthreads();
    }
    if (t == 0) {
        float m = (float)(s[0] / (double)TOTAL);   // mean((q-lat)^2)
        // vq_loss = commitment*0.25 + embedding, both equal m in fwd
        out[out_size - 1] = __fadd_rn(__fmul_rn(m, 0.25f), m);
    }
}

extern "C" void kernel_launch(void* const* d_in, const int* in_sizes, int n_in,
                              void* d_out, int out_size) {
    const float* lat = (const float*)d_in[0];
    const float* W   = (const float*)d_in[1];
    float* out = (float*)d_out;

    const int smem_bytes = KCODES * DCH * 4 + KCODES * 4 + TPB * 8;  // 135168
    cudaFuncSetAttribute(vq_main, cudaFuncAttributeMaxDynamicSharedMemorySize, smem_bytes);

    vq_main<<<NBLOCKS, TPB, smem_bytes>>>(lat, W, out);
    vq_finish<<<1, NBLOCKS>>>(out, out_size);
}